// round 9
// baseline (speedup 1.0000x reference)
#include <cuda_runtime.h>
#include <math_constants.h>

// TropicalLinear forward: out[n,o] = max_j( x[n,j] + w[o,j] ) + bias[o]
//
// 128 blocks x 1024 threads (8 warps/SMSP for latency cover).
// Block tile 32n x 32o, full K. 16 k-groups x 2 warps; warp pair g handles
// 16B-granule g of each 64-k slab; within a pair, warp `half` computes rows
// [16*half, 16*half+16) with a 4x4 register tile (rows +4r, cols +8c).
// Per warp per iter: 8 LDS.128 + 128 math (crossbar-safe), ~55 regs.
// Double-buffered smem, padded strides; in-kernel 16->8->1 max-reduction.

#define N_DIM   128
#define IN_DIM  1024
#define OUT_DIM 1024
#define BMT     32
#define BOT     32
#define BKT     64              // k staged per iteration
#define NITER   (IN_DIM / BKT)  // 16
#define TSTR    68              // tile row stride (17 granules, odd)
#define TBUF    (BMT * TSTR)    // 2176 floats per tile buffer
#define RSTR    40              // reduction row stride: 40*ty mod 32 = 8*ty -> conflict-free
#define RSZ     (BMT * RSTR)    // 1280 floats per partial region

__global__ __launch_bounds__(1024, 1)
void tropical_kernel(const float* __restrict__ x,
                     const float* __restrict__ w,
                     const float* __restrict__ bias,
                     float* __restrict__ out)
{
    // arena: tiles (4*TBUF = 8704 floats) UNION reduction (8*RSZ = 10240 floats)
    __shared__ float sm[8 * RSZ];
#define XS(b) (sm + (b) * TBUF)
#define WS(b) (sm + 2 * TBUF + (b) * TBUF)

    const int t    = threadIdx.x;
    const int g    = t >> 6;          // k-group 0..15 (warp pair)
    const int half = (t >> 5) & 1;    // which 16-row half of the tile
    const int lane = t & 31;
    const int tx   = lane & 7;        // o cols: tx + 8c, c=0..3
    const int ty   = lane >> 3;       // 0..3 -> n rows: 16*half + ty + 4r
    const int oBase = blockIdx.x * BOT;
    const int nBase = blockIdx.y * BMT;

    // loaders: warps 0..15 stage x-tile, warps 16..31 stage w-tile.
    // Each thread: exactly one float4 (row lrow, granule lgran) per slab.
    const int isx   = (t < 512);
    const int lrow  = (t >> 4) & 31;
    const int lgran = t & 15;
    const float* src = (isx ? x + (nBase + lrow) * IN_DIM
                            : w + (oBase + lrow) * IN_DIM) + (lgran << 2);
    const int sidx = (isx ? 0 : 2 * TBUF) + lrow * TSTR + (lgran << 2);

    const int goff = g << 2;          // group granule's float offset in a row

    float acc[4][4];
#pragma unroll
    for (int r = 0; r < 4; r++)
#pragma unroll
        for (int c = 0; c < 4; c++)
            acc[r][c] = -CUDART_INF_F;

    float4 pref;

    // ---- prologue: slab 0 -> buffer 0 ----
    pref = *(const float4*)src;
    *(float4*)&sm[0 * TBUF + sidx] = pref;   // buffer 0 region (xs or ws half)
    __syncthreads();

#define COMPUTE(b)                                                          \
    {                                                                       \
        const float* px = XS(b) + (half * 16 + ty) * TSTR + goff;           \
        const float* pw = WS(b) + tx * TSTR + goff;                         \
        const float4 a0 = *(const float4*)(px);                             \
        const float4 a1 = *(const float4*)(px + 4 * TSTR);                  \
        const float4 a2 = *(const float4*)(px + 8 * TSTR);                  \
        const float4 a3 = *(const float4*)(px + 12 * TSTR);                 \
        _Pragma("unroll")                                                   \
        for (int c = 0; c < 4; c++) {                                       \
            const float4 bv = *(const float4*)(pw + c * (8 * TSTR));        \
            acc[0][c] = fmaxf(acc[0][c], a0.x + bv.x);                      \
            acc[0][c] = fmaxf(acc[0][c], a0.y + bv.y);                      \
            acc[0][c] = fmaxf(acc[0][c], a0.z + bv.z);                      \
            acc[0][c] = fmaxf(acc[0][c], a0.w + bv.w);                      \
            acc[1][c] = fmaxf(acc[1][c], a1.x + bv.x);                      \
            acc[1][c] = fmaxf(acc[1][c], a1.y + bv.y);                      \
            acc[1][c] = fmaxf(acc[1][c], a1.z + bv.z);                      \
            acc[1][c] = fmaxf(acc[1][c], a1.w + bv.w);                      \
            acc[2][c] = fmaxf(acc[2][c], a2.x + bv.x);                      \
            acc[2][c] = fmaxf(acc[2][c], a2.y + bv.y);                      \
            acc[2][c] = fmaxf(acc[2][c], a2.z + bv.z);                      \
            acc[2][c] = fmaxf(acc[2][c], a2.w + bv.w);                      \
            acc[3][c] = fmaxf(acc[3][c], a3.x + bv.x);                      \
            acc[3][c] = fmaxf(acc[3][c], a3.y + bv.y);                      \
            acc[3][c] = fmaxf(acc[3][c], a3.z + bv.z);                      \
            acc[3][c] = fmaxf(acc[3][c], a3.w + bv.w);                      \
        }                                                                   \
    }

#pragma unroll 1
    for (int i = 0; i < NITER - 1; i++) {
        const int b = i & 1;

        // prefetch next slab (one LDG/thread; latency hidden under compute)
        pref = *(const float4*)(src + (i + 1) * BKT);

        COMPUTE(b)

        const int nb = b ^ 1;
        *(float4*)&sm[nb * TBUF + sidx] = pref;
        __syncthreads();
    }

    COMPUTE(1)   // slab 15 lives in buffer 1

    // ---- cross-group reduction: 16 -> 8 -> 1 (reuses the smem arena) ----
    __syncthreads();                       // all tile reads done before overwrite

    // stage A: groups 8..15 park partials in region g-8
    if (g >= 8) {
        float* red = sm + (g - 8) * RSZ;
#pragma unroll
        for (int r = 0; r < 4; r++)
#pragma unroll
            for (int c = 0; c < 4; c++)
                red[(half * 16 + ty + 4 * r) * RSTR + tx + 8 * c] = acc[r][c];
    }
    __syncthreads();

    // stage B: groups 0..7 merge their accs into region g
    if (g < 8) {
        float* red = sm + g * RSZ;
#pragma unroll
        for (int r = 0; r < 4; r++)
#pragma unroll
            for (int c = 0; c < 4; c++) {
                const int off = (half * 16 + ty + 4 * r) * RSTR + tx + 8 * c;
                red[off] = fmaxf(red[off], acc[r][c]);
            }
    }
    __syncthreads();

    // stage C: 8-way max + bias + store; exactly 1 output per thread
    {
        const int n = t >> 5;
        const int o = t & 31;
        const int ro = n * RSTR + o;
        float v0 = fmaxf(sm[ro],           sm[ro + RSZ]);
        float v1 = fmaxf(sm[ro + 2 * RSZ], sm[ro + 3 * RSZ]);
        float v2 = fmaxf(sm[ro + 4 * RSZ], sm[ro + 5 * RSZ]);
        float v3 = fmaxf(sm[ro + 6 * RSZ], sm[ro + 7 * RSZ]);
        float v  = fmaxf(fmaxf(v0, v1), fmaxf(v2, v3));
        out[(nBase + n) * OUT_DIM + oBase + o] = v + bias[oBase + o];
    }
}

extern "C" void kernel_launch(void* const* d_in, const int* in_sizes, int n_in,
                              void* d_out, int out_size)
{
    const float* x    = (const float*)d_in[0];   // [128, 1024]
    const float* w    = (const float*)d_in[1];   // [1024, 1024]
    const float* bias = (const float*)d_in[2];   // [1024]
    float* out = (float*)d_out;                  // [128, 1024]

    dim3 grid(OUT_DIM / BOT, N_DIM / BMT);       // 32 x 4 = 128 blocks
    tropical_kernel<<<grid, 1024>>>(x, w, bias, out);
}

// round 10
// speedup vs baseline: 1.2035x; 1.2035x over previous
#include <cuda_runtime.h>
#include <math_constants.h>

// TropicalLinear forward: out[n,o] = max_j( x[n,j] + w[o,j] ) + bias[o]
//
// 128 blocks x 512 threads. Block tile 32n x 32o, full K.
// BKT=128 -> only 8 iterations / 8 barriers (seam-hole amortization).
// 16 k-groups (1 warp each): warp g handles granules 2g,2g+1 of each slab
// (8 k's/slab, 64 k's total), computing the whole 32x32 tile with a 4x8
// register tile. Per warp per iter: 24 LDS.128 + 512 math.
// Dynamic smem (66KB): 2 double-buffered 32x128 tiles, row stride 132.
// In-kernel 16->8->1 smem max-reduction.

#define N_DIM   128
#define IN_DIM  1024
#define OUT_DIM 1024
#define BMT     32
#define BOT     32
#define BKT     128             // k staged per iteration
#define NITER   (IN_DIM / BKT)  // 8
#define TSTR    132             // tile row stride in floats (33 granules, odd)
#define TBUF    (BMT * TSTR)    // 4224 floats per tile buffer
#define SMEM_BYTES (4 * TBUF * 4)   // xs0,xs1,ws0,ws1 = 67584 B
#define RSTR    36              // reduction row stride (4ty+tx distinct mod 32)
#define RSZ     (BMT * RSTR)    // 1152 floats per partial region

extern __shared__ float sm[];
#define XS(b) (sm + (b) * TBUF)
#define WS(b) (sm + 2 * TBUF + (b) * TBUF)

__global__ __launch_bounds__(512, 1)
void tropical_kernel(const float* __restrict__ x,
                     const float* __restrict__ w,
                     const float* __restrict__ bias,
                     float* __restrict__ out)
{
    const int t    = threadIdx.x;
    const int g    = t >> 5;         // k-group == warp id, 0..15
    const int lane = t & 31;
    const int tx   = lane & 3;       // o cols: tx + 4c, c=0..7
    const int ty   = lane >> 2;      // n rows: ty + 8r, r=0..3
    const int oBase = blockIdx.x * BOT;
    const int nBase = blockIdx.y * BMT;

    // loaders: each thread stages 2 granules of x-tile and 2 of w-tile per slab
    const int lrow  = t >> 4;        // 0..31
    const int lgran = t & 15;        // granules lgran, lgran+16
    const float* xg = x + (nBase + lrow) * IN_DIM + (lgran << 2);
    const float* wg = w + (oBase + lrow) * IN_DIM + (lgran << 2);
    const int s0 = lrow * TSTR + (lgran << 2);   // granule lgran slot
    const int s1 = s0 + 64;                      // granule lgran+16 slot

    const int goff = g << 3;         // float offset of granule 2g in a row

    float acc[4][8];
#pragma unroll
    for (int r = 0; r < 4; r++)
#pragma unroll
        for (int c = 0; c < 8; c++)
            acc[r][c] = -CUDART_INF_F;

    float4 xr0, xr1, wr0, wr1;

    // ---- prologue: slab 0 -> buffer 0 ----
    xr0 = *(const float4*)(xg);
    xr1 = *(const float4*)(xg + 64);
    wr0 = *(const float4*)(wg);
    wr1 = *(const float4*)(wg + 64);
    *(float4*)&XS(0)[s0] = xr0;
    *(float4*)&XS(0)[s1] = xr1;
    *(float4*)&WS(0)[s0] = wr0;
    *(float4*)&WS(0)[s1] = wr1;
    __syncthreads();

    // one granule's worth of math: 4 a-vec rows x 8 b-vec cols
#define GRANULE(b, G)                                                       \
    {                                                                       \
        const float* px = XS(b) + ty * TSTR + (G);                          \
        const float* pw = WS(b) + tx * TSTR + (G);                          \
        const float4 a0 = *(const float4*)(px);                             \
        const float4 a1 = *(const float4*)(px + 8 * TSTR);                  \
        const float4 a2 = *(const float4*)(px + 16 * TSTR);                 \
        const float4 a3 = *(const float4*)(px + 24 * TSTR);                 \
        _Pragma("unroll")                                                   \
        for (int c = 0; c < 8; c++) {                                       \
            const float4 bv = *(const float4*)(pw + c * (4 * TSTR));        \
            acc[0][c] = fmaxf(acc[0][c], a0.x + bv.x);                      \
            acc[0][c] = fmaxf(acc[0][c], a0.y + bv.y);                      \
            acc[0][c] = fmaxf(acc[0][c], a0.z + bv.z);                      \
            acc[0][c] = fmaxf(acc[0][c], a0.w + bv.w);                      \
            acc[1][c] = fmaxf(acc[1][c], a1.x + bv.x);                      \
            acc[1][c] = fmaxf(acc[1][c], a1.y + bv.y);                      \
            acc[1][c] = fmaxf(acc[1][c], a1.z + bv.z);                      \
            acc[1][c] = fmaxf(acc[1][c], a1.w + bv.w);                      \
            acc[2][c] = fmaxf(acc[2][c], a2.x + bv.x);                      \
            acc[2][c] = fmaxf(acc[2][c], a2.y + bv.y);                      \
            acc[2][c] = fmaxf(acc[2][c], a2.z + bv.z);                      \
            acc[2][c] = fmaxf(acc[2][c], a2.w + bv.w);                      \
            acc[3][c] = fmaxf(acc[3][c], a3.x + bv.x);                      \
            acc[3][c] = fmaxf(acc[3][c], a3.y + bv.y);                      \
            acc[3][c] = fmaxf(acc[3][c], a3.z + bv.z);                      \
            acc[3][c] = fmaxf(acc[3][c], a3.w + bv.w);                      \
        }                                                                   \
    }

#pragma unroll 1
    for (int i = 0; i < NITER - 1; i++) {
        const int b = i & 1;

        // prefetch next slab (4 LDG/thread, latency hidden under 512 math)
        const float* xp = xg + (i + 1) * BKT;
        const float* wp = wg + (i + 1) * BKT;
        xr0 = *(const float4*)(xp);
        xr1 = *(const float4*)(xp + 64);
        wr0 = *(const float4*)(wp);
        wr1 = *(const float4*)(wp + 64);

        GRANULE(b, goff)
        GRANULE(b, goff + 4)

        const int nb = b ^ 1;
        *(float4*)&XS(nb)[s0] = xr0;
        *(float4*)&XS(nb)[s1] = xr1;
        *(float4*)&WS(nb)[s0] = wr0;
        *(float4*)&WS(nb)[s1] = wr1;
        __syncthreads();
    }

    // final slab (7) is in buffer 1
    GRANULE(1, goff)
    GRANULE(1, goff + 4)

    // ---- cross-group reduction: 16 -> 8 -> 1 (reuses the smem arena) ----
    __syncthreads();                       // all tile reads done before overwrite

    // stage A: groups 8..15 park partials in region g-8
    if (g >= 8) {
        float* red = sm + (g - 8) * RSZ;
#pragma unroll
        for (int r = 0; r < 4; r++)
#pragma unroll
            for (int c = 0; c < 8; c++)
                red[(ty + 8 * r) * RSTR + tx + 4 * c] = acc[r][c];
    }
    __syncthreads();

    // stage B: groups 0..7 merge their accs into region g
    if (g < 8) {
        float* red = sm + g * RSZ;
#pragma unroll
        for (int r = 0; r < 4; r++)
#pragma unroll
            for (int c = 0; c < 8; c++) {
                const int off = (ty + 8 * r) * RSTR + tx + 4 * c;
                red[off] = fmaxf(red[off], acc[r][c]);
            }
    }
    __syncthreads();

    // stage C: 8-way max + bias + store; 2 outputs per thread
#pragma unroll
    for (int j = 0; j < 2; j++) {
        const int idx = t + j * 512;       // 0..1023
        const int n = idx >> 5;
        const int o = idx & 31;
        const int ro = n * RSTR + o;
        float v0 = fmaxf(sm[ro],           sm[ro + RSZ]);
        float v1 = fmaxf(sm[ro + 2 * RSZ], sm[ro + 3 * RSZ]);
        float v2 = fmaxf(sm[ro + 4 * RSZ], sm[ro + 5 * RSZ]);
        float v3 = fmaxf(sm[ro + 6 * RSZ], sm[ro + 7 * RSZ]);
        float v  = fmaxf(fmaxf(v0, v1), fmaxf(v2, v3));
        out[(nBase + n) * OUT_DIM + oBase + o] = v + bias[oBase + o];
    }
}

extern "C" void kernel_launch(void* const* d_in, const int* in_sizes, int n_in,
                              void* d_out, int out_size)
{
    const float* x    = (const float*)d_in[0];   // [128, 1024]
    const float* w    = (const float*)d_in[1];   // [1024, 1024]
    const float* bias = (const float*)d_in[2];   // [1024]
    float* out = (float*)d_out;                  // [128, 1024]

    // 66KB dynamic smem > 48KB default -> opt-in (attribute set, not an alloc;
    // idempotent and deterministic on every call)
    cudaFuncSetAttribute(tropical_kernel,
                         cudaFuncAttributeMaxDynamicSharedMemorySize, SMEM_BYTES);

    dim3 grid(OUT_DIM / BOT, N_DIM / BMT);       // 32 x 4 = 128 blocks
    tropical_kernel<<<grid, 512, SMEM_BYTES>>>(x, w, bias, out);
}